// round 1
// baseline (speedup 1.0000x reference)
#include <cuda_runtime.h>

#define B_  4
#define S_  2048
#define D_  1024
#define H_  16
#define HD_ 64
#define M_  (B_*S_)

// Scratch (device globals — no allocation allowed in kernel_launch)
__device__ float g_xq[B_*H_*S_*HD_];   // [B,H,S,HD]
__device__ float g_xk[B_*H_*S_*HD_];
__device__ float g_xv[B_*H_*S_*HD_];
__device__ float g_att[B_*S_*D_];      // [B,S,D]

// ---------------------------------------------------------------------------
// GEMM: C[m,n] = sum_k A[m,k] * W[n,k]   (A: [M_,1024] row-major, W: [1024,1024])
// permute=1: write to [B,H,S,HD] layout (QKV projections). permute=0: [M_,D_].
// 64x64 tile, BK=16, 256 threads, 4x4 micro-tile.
// ---------------------------------------------------------------------------
__global__ __launch_bounds__(256) void gemm_xwt(const float* __restrict__ A,
                                                const float* __restrict__ W,
                                                float* __restrict__ C,
                                                int permute)
{
    __shared__ float As[16][64];   // [k][m]
    __shared__ float Ws[16][64];   // [k][n]
    const int m0 = blockIdx.y * 64;
    const int n0 = blockIdx.x * 64;
    const int tid = threadIdx.x;
    const int tx = tid & 15, ty = tid >> 4;
    const int lr = tid >> 2, lq = tid & 3;

    const float* Ap = A + (size_t)(m0 + lr) * D_ + lq * 4;
    const float* Wp = W + (size_t)(n0 + lr) * D_ + lq * 4;

    float acc[4][4] = {};
    for (int k0 = 0; k0 < D_; k0 += 16) {
        float4 av = *reinterpret_cast<const float4*>(Ap + k0);
        float4 wv = *reinterpret_cast<const float4*>(Wp + k0);
        __syncthreads();
        As[lq*4+0][lr] = av.x; As[lq*4+1][lr] = av.y;
        As[lq*4+2][lr] = av.z; As[lq*4+3][lr] = av.w;
        Ws[lq*4+0][lr] = wv.x; Ws[lq*4+1][lr] = wv.y;
        Ws[lq*4+2][lr] = wv.z; Ws[lq*4+3][lr] = wv.w;
        __syncthreads();
        #pragma unroll
        for (int k = 0; k < 16; k++) {
            float4 a = *reinterpret_cast<const float4*>(&As[k][ty*4]);
            float4 b = *reinterpret_cast<const float4*>(&Ws[k][tx*4]);
            float av4[4] = {a.x, a.y, a.z, a.w};
            float bv4[4] = {b.x, b.y, b.z, b.w};
            #pragma unroll
            for (int i = 0; i < 4; i++)
                #pragma unroll
                for (int j = 0; j < 4; j++)
                    acc[i][j] += av4[i] * bv4[j];
        }
    }
    #pragma unroll
    for (int i = 0; i < 4; i++) {
        int m = m0 + ty*4 + i;
        #pragma unroll
        for (int j = 0; j < 4; j++) {
            int n = n0 + tx*4 + j;
            if (permute) {
                int b = m >> 11;            // /S_
                int s = m & (S_ - 1);
                int h = n >> 6;             // /HD_
                int hd = n & (HD_ - 1);
                g_att[0];                   // no-op keep symbol (optimized away)
                C[(((size_t)(b*H_ + h) * S_ + s) * HD_) + hd] = acc[i][j];
            } else {
                C[(size_t)m * D_ + n] = acc[i][j];
            }
        }
    }
}

// ---------------------------------------------------------------------------
// Flash attention: one CTA per (b, h, 64-row q tile). 256 threads.
// smem: Qst/Kst d-major [64][68], Vs [j][68], Ps [j][68]. Online softmax.
// ---------------------------------------------------------------------------
#define TSTRIDE 68
#define ATTN_SMEM (4 * 64 * TSTRIDE * (int)sizeof(float))

__global__ __launch_bounds__(256) void attn_fwd(const float* __restrict__ XQ,
                                                const float* __restrict__ XK,
                                                const float* __restrict__ XV,
                                                float* __restrict__ O)
{
    extern __shared__ float sm[];
    float* Qst = sm;                    // [d][r]  scaled by 1/8
    float* Kst = sm + 64*TSTRIDE;       // [d][j]
    float* Vs  = sm + 2*64*TSTRIDE;     // [j][d]
    float* Ps  = sm + 3*64*TSTRIDE;     // [j][r]

    const int qb = blockIdx.x;
    const int h  = blockIdx.y;
    const int b  = blockIdx.z;
    const size_t base = (size_t)(b*H_ + h) * S_ * HD_;
    const float* Q = XQ + base;
    const float* K = XK + base;
    const float* V = XV + base;

    const int tid = threadIdx.x;
    const int tx = tid & 15, ty = tid >> 4;
    const int lr = tid >> 2, lq = tid & 3;
    const int q0 = qb * 64;

    // Load Q tile transposed (d-major), fold in 1/sqrt(HD) = 0.125
    {
        const float* src = Q + (size_t)(q0 + lr) * HD_ + lq*16;
        #pragma unroll
        for (int c = 0; c < 4; c++) {
            float4 v = reinterpret_cast<const float4*>(src)[c];
            int d = lq*16 + c*4;
            Qst[(d+0)*TSTRIDE + lr] = v.x * 0.125f;
            Qst[(d+1)*TSTRIDE + lr] = v.y * 0.125f;
            Qst[(d+2)*TSTRIDE + lr] = v.z * 0.125f;
            Qst[(d+3)*TSTRIDE + lr] = v.w * 0.125f;
        }
    }

    float oacc[4][4] = {};
    float mrow[4], lrow[4];
    #pragma unroll
    for (int i = 0; i < 4; i++) { mrow[i] = -1e30f; lrow[i] = 0.f; }

    for (int kb = 0; kb <= qb; kb++) {
        const int k0 = kb * 64;
        __syncthreads();   // previous iter done reading Kst/Vs/Ps (also fences Q store)
        {
            const float* srcK = K + (size_t)(k0 + lr) * HD_ + lq*16;
            const float* srcV = V + (size_t)(k0 + lr) * HD_ + lq*16;
            #pragma unroll
            for (int c = 0; c < 4; c++) {
                float4 kv = reinterpret_cast<const float4*>(srcK)[c];
                int d = lq*16 + c*4;
                Kst[(d+0)*TSTRIDE + lr] = kv.x;
                Kst[(d+1)*TSTRIDE + lr] = kv.y;
                Kst[(d+2)*TSTRIDE + lr] = kv.z;
                Kst[(d+3)*TSTRIDE + lr] = kv.w;
                float4 vv = reinterpret_cast<const float4*>(srcV)[c];
                *reinterpret_cast<float4*>(&Vs[lr*TSTRIDE + lq*16 + c*4]) = vv;
            }
        }
        __syncthreads();

        // S = (Q/8) @ K^T  -> 4x4 per thread
        float sacc[4][4] = {};
        #pragma unroll 8
        for (int d = 0; d < 64; d++) {
            float4 a  = *reinterpret_cast<const float4*>(&Qst[d*TSTRIDE + ty*4]);
            float4 bv = *reinterpret_cast<const float4*>(&Kst[d*TSTRIDE + tx*4]);
            float av4[4] = {a.x, a.y, a.z, a.w};
            float bv4[4] = {bv.x, bv.y, bv.z, bv.w};
            #pragma unroll
            for (int i = 0; i < 4; i++)
                #pragma unroll
                for (int j = 0; j < 4; j++)
                    sacc[i][j] += av4[i] * bv4[j];
        }

        if (kb == qb) {   // causal mask on diagonal block
            #pragma unroll
            for (int i = 0; i < 4; i++)
                #pragma unroll
                for (int j = 0; j < 4; j++)
                    if (k0 + tx*4 + j > q0 + ty*4 + i) sacc[i][j] = -1e30f;
        }

        // Online softmax; rows owned per-ty across 16 tx lanes (shfl width 16)
        #pragma unroll
        for (int i = 0; i < 4; i++) {
            float rm = fmaxf(fmaxf(sacc[i][0], sacc[i][1]),
                             fmaxf(sacc[i][2], sacc[i][3]));
            #pragma unroll
            for (int off = 1; off < 16; off <<= 1)
                rm = fmaxf(rm, __shfl_xor_sync(0xffffffffu, rm, off));
            float mn   = fmaxf(mrow[i], rm);
            float corr = __expf(mrow[i] - mn);
            mrow[i] = mn;
            float rs = 0.f;
            #pragma unroll
            for (int j = 0; j < 4; j++) {
                float p = __expf(sacc[i][j] - mn);
                rs += p;
                Ps[(tx*4 + j)*TSTRIDE + ty*4 + i] = p;   // transposed for PV
            }
            #pragma unroll
            for (int off = 1; off < 16; off <<= 1)
                rs += __shfl_xor_sync(0xffffffffu, rs, off);
            lrow[i] = lrow[i]*corr + rs;
            #pragma unroll
            for (int j = 0; j < 4; j++) oacc[i][j] *= corr;
        }
        __syncthreads();

        // O += P @ V
        #pragma unroll 8
        for (int j = 0; j < 64; j++) {
            float4 p  = *reinterpret_cast<const float4*>(&Ps[j*TSTRIDE + ty*4]);
            float4 vv = *reinterpret_cast<const float4*>(&Vs[j*TSTRIDE + tx*4]);
            float pv4[4] = {p.x, p.y, p.z, p.w};
            float vv4[4] = {vv.x, vv.y, vv.z, vv.w};
            #pragma unroll
            for (int i = 0; i < 4; i++)
                #pragma unroll
                for (int c = 0; c < 4; c++)
                    oacc[i][c] += pv4[i] * vv4[c];
        }
    }

    #pragma unroll
    for (int i = 0; i < 4; i++) {
        float inv = 1.f / lrow[i];
        size_t row = (size_t)(b * S_ + q0 + ty*4 + i) * D_ + h*HD_ + tx*4;
        #pragma unroll
        for (int j = 0; j < 4; j++)
            O[row + j] = oacc[i][j] * inv;
    }
}

// ---------------------------------------------------------------------------
extern "C" void kernel_launch(void* const* d_in, const int* in_sizes, int n_in,
                              void* d_out, int out_size)
{
    const float* q  = (const float*)d_in[0];
    const float* k  = (const float*)d_in[1];
    const float* v  = (const float*)d_in[2];
    const float* wq = (const float*)d_in[3];
    const float* wk = (const float*)d_in[4];
    const float* wv = (const float*)d_in[5];
    const float* wo = (const float*)d_in[6];
    float* out = (float*)d_out;

    void *xq_p, *xk_p, *xv_p, *att_p;
    cudaGetSymbolAddress(&xq_p,  g_xq);
    cudaGetSymbolAddress(&xk_p,  g_xk);
    cudaGetSymbolAddress(&xv_p,  g_xv);
    cudaGetSymbolAddress(&att_p, g_att);

    cudaFuncSetAttribute(attn_fwd, cudaFuncAttributeMaxDynamicSharedMemorySize,
                         ATTN_SMEM);

    dim3 ggrid(D_/64, M_/64);   // (16, 128)
    gemm_xwt<<<ggrid, 256>>>(q, wq, (float*)xq_p, 1);
    gemm_xwt<<<ggrid, 256>>>(k, wk, (float*)xk_p, 1);
    gemm_xwt<<<ggrid, 256>>>(v, wv, (float*)xv_p, 1);

    dim3 agrid(S_/64, H_, B_);  // (32, 16, 4)
    attn_fwd<<<agrid, 256, ATTN_SMEM>>>((const float*)xq_p, (const float*)xk_p,
                                        (const float*)xv_p, (float*)att_p);

    gemm_xwt<<<ggrid, 256>>>((const float*)att_p, wo, out, 0);
}

// round 3
// speedup vs baseline: 1.7529x; 1.7529x over previous
#include <cuda_runtime.h>
#include <cstdint>

#define B_  4
#define S_  2048
#define D_  1024
#define H_  16
#define HD_ 64
#define M_  (B_*S_)

// Scratch (device globals — no allocation allowed in kernel_launch)
__device__ float g_xq[B_*H_*S_*HD_];   // [B,H,S,HD]
__device__ float g_xk[B_*H_*S_*HD_];
__device__ float g_xv[B_*H_*S_*HD_];
__device__ float g_att[B_*S_*D_];      // [B,S,D]

// ===========================================================================
// Portable tensor-core helpers (compile under compute_103: mma.sync + ldmatrix)
// ===========================================================================
__device__ __forceinline__ uint32_t smem_u32(const void* p) {
    uint32_t a;
    asm("{ .reg .u64 t; cvta.to.shared.u64 t, %1; cvt.u32.u64 %0, t; }"
        : "=r"(a) : "l"(p));
    return a;
}
// pack two fp32 -> bf16x2, lo_f in low half
__device__ __forceinline__ uint32_t packbf(float lo_f, float hi_f) {
    uint32_t r;
    asm("cvt.rn.bf16x2.f32 %0, %1, %2;" : "=r"(r) : "f"(hi_f), "f"(lo_f));
    return r;
}
__device__ __forceinline__ void ldm_x4(uint32_t* r, uint32_t a) {
    asm volatile("ldmatrix.sync.aligned.m8n8.x4.shared.b16 {%0,%1,%2,%3}, [%4];"
        : "=r"(r[0]), "=r"(r[1]), "=r"(r[2]), "=r"(r[3]) : "r"(a));
}
__device__ __forceinline__ void mma_bf(float* c, const uint32_t* a, const uint32_t* b) {
    asm volatile("mma.sync.aligned.m16n8k16.row.col.f32.bf16.bf16.f32 "
        "{%0,%1,%2,%3}, {%4,%5,%6,%7}, {%8,%9}, {%0,%1,%2,%3};"
        : "+f"(c[0]), "+f"(c[1]), "+f"(c[2]), "+f"(c[3])
        : "r"(a[0]), "r"(a[1]), "r"(a[2]), "r"(a[3]), "r"(b[0]), "r"(b[1]));
}

// Swizzled byte offset inside a 128x32-bf16 tile (64B rows, 16B chunks)
#define SWZB(row, ch) ((uint32_t)((row)*64 + ((((ch) ^ (((row)>>1)&3)))<<4)))

// fp32x8 -> bf16 hi chunk (16B) + lo chunk (16B)
__device__ __forceinline__ void cvt16(float4 x, float4 y, char* hip, char* lop) {
    uint32_t h0 = packbf(x.x, x.y), h1 = packbf(x.z, x.w);
    uint32_t h2 = packbf(y.x, y.y), h3 = packbf(y.z, y.w);
    float e0 = x.x - __uint_as_float(h0 << 16);
    float e1 = x.y - __uint_as_float(h0 & 0xffff0000u);
    float e2 = x.z - __uint_as_float(h1 << 16);
    float e3 = x.w - __uint_as_float(h1 & 0xffff0000u);
    float e4 = y.x - __uint_as_float(h2 << 16);
    float e5 = y.y - __uint_as_float(h2 & 0xffff0000u);
    float e6 = y.z - __uint_as_float(h3 << 16);
    float e7 = y.w - __uint_as_float(h3 & 0xffff0000u);
    *reinterpret_cast<uint4*>(hip) = make_uint4(h0, h1, h2, h3);
    *reinterpret_cast<uint4*>(lop) =
        make_uint4(packbf(e0,e1), packbf(e2,e3), packbf(e4,e5), packbf(e6,e7));
}

// ===========================================================================
// bf16x3 tensor-core GEMM: C[m,n] = sum_k A[m,k]*W[n,k]
// CTA 128x128, BK=32, 256 threads (8 warps, each 64x32), double-buffered SMEM.
// Stage layout (32KB): Ah@0, Al@8192, Bh@16384, Bl@24576. 2 stages = 64KB.
// ===========================================================================
#define GSTAGE 32768
#define GSMEM  (2*GSTAGE)

__global__ __launch_bounds__(256) void gemm_mma(const float* __restrict__ A,
                                                const float* __restrict__ W,
                                                float* __restrict__ C,
                                                int permute)
{
    extern __shared__ char smem[];
    const uint32_t sb = smem_u32(smem);
    const int tid = threadIdx.x, lane = tid & 31, wid = tid >> 5;
    const int warp_m = wid & 1, warp_n = wid >> 1;
    const int m0 = blockIdx.y * 128, n0 = blockIdx.x * 128;

    // global load mapping: 2 threads per row, 16 floats each
    const int grow = tid >> 1, kp = tid & 1;
    const float* Ap = A + (size_t)(m0 + grow) * D_ + kp * 16;
    const float* Wp = W + (size_t)(n0 + grow) * D_ + kp * 16;
    const uint32_t o0 = SWZB(grow, kp*2);
    const uint32_t o1 = SWZB(grow, kp*2 + 1);

    // ldmatrix address components
    const int arow = warp_m*64 + (lane & 7) + ((lane >> 3) & 1) * 8;  // + mt*16
    const int akb  = lane >> 4;
    const int axr  = (arow >> 1) & 3;   // invariant under +mt*16
    const int brow = warp_n*32 + ((lane >> 4) & 1) * 8 + (lane & 7);  // + ntp*16
    const int bkb  = (lane >> 3) & 1;
    const int bxr  = (brow >> 1) & 3;

    float acc[4][4][4];
    #pragma unroll
    for (int i = 0; i < 4; i++)
        #pragma unroll
        for (int j = 0; j < 4; j++)
            #pragma unroll
            for (int r = 0; r < 4; r++) acc[i][j][r] = 0.f;

    float4 fa0, fa1, fa2, fa3, fb0, fb1, fb2, fb3;
    fa0 = reinterpret_cast<const float4*>(Ap)[0];
    fa1 = reinterpret_cast<const float4*>(Ap)[1];
    fa2 = reinterpret_cast<const float4*>(Ap)[2];
    fa3 = reinterpret_cast<const float4*>(Ap)[3];
    fb0 = reinterpret_cast<const float4*>(Wp)[0];
    fb1 = reinterpret_cast<const float4*>(Wp)[1];
    fb2 = reinterpret_cast<const float4*>(Wp)[2];
    fb3 = reinterpret_cast<const float4*>(Wp)[3];

    for (int ch = 0; ch < 32; ch++) {
        char* sp = smem + (ch & 1) * GSTAGE;
        cvt16(fa0, fa1, sp + o0,         sp + 8192  + o0);
        cvt16(fa2, fa3, sp + o1,         sp + 8192  + o1);
        cvt16(fb0, fb1, sp + 16384 + o0, sp + 24576 + o0);
        cvt16(fb2, fb3, sp + 16384 + o1, sp + 24576 + o1);
        __syncthreads();
        if (ch < 31) {
            const float* pa = Ap + (ch + 1) * 32;
            const float* pb = Wp + (ch + 1) * 32;
            fa0 = reinterpret_cast<const float4*>(pa)[0];
            fa1 = reinterpret_cast<const float4*>(pa)[1];
            fa2 = reinterpret_cast<const float4*>(pa)[2];
            fa3 = reinterpret_cast<const float4*>(pa)[3];
            fb0 = reinterpret_cast<const float4*>(pb)[0];
            fb1 = reinterpret_cast<const float4*>(pb)[1];
            fb2 = reinterpret_cast<const float4*>(pb)[2];
            fb3 = reinterpret_cast<const float4*>(pb)[3];
        }
        const uint32_t ss = sb + (ch & 1) * GSTAGE;
        #pragma unroll
        for (int ks = 0; ks < 2; ks++) {
            uint32_t ah[4][4], al[4][4], bh[2][4], bl[2][4];
            #pragma unroll
            for (int mt = 0; mt < 4; mt++) {
                uint32_t ao = (uint32_t)((arow + mt*16)*64)
                            + ((uint32_t)((ks*2 + akb) ^ axr) << 4);
                ldm_x4(ah[mt], ss + ao);
                ldm_x4(al[mt], ss + 8192 + ao);
            }
            #pragma unroll
            for (int ntp = 0; ntp < 2; ntp++) {
                uint32_t bo = (uint32_t)((brow + ntp*16)*64)
                            + ((uint32_t)((ks*2 + bkb) ^ bxr) << 4);
                ldm_x4(bh[ntp], ss + 16384 + bo);
                ldm_x4(bl[ntp], ss + 24576 + bo);
            }
            #pragma unroll
            for (int mt = 0; mt < 4; mt++)
                #pragma unroll
                for (int nt = 0; nt < 4; nt++)
                    mma_bf(acc[mt][nt], ah[mt], &bh[nt >> 1][(nt & 1) * 2]);
            #pragma unroll
            for (int mt = 0; mt < 4; mt++)
                #pragma unroll
                for (int nt = 0; nt < 4; nt++)
                    mma_bf(acc[mt][nt], al[mt], &bh[nt >> 1][(nt & 1) * 2]);
            #pragma unroll
            for (int mt = 0; mt < 4; mt++)
                #pragma unroll
                for (int nt = 0; nt < 4; nt++)
                    mma_bf(acc[mt][nt], ah[mt], &bl[nt >> 1][(nt & 1) * 2]);
        }
    }

    // Epilogue
    const int r4 = lane >> 2, c2 = (lane & 3) * 2;
    #pragma unroll
    for (int mt = 0; mt < 4; mt++) {
        const int m = m0 + warp_m*64 + mt*16 + r4;
        #pragma unroll
        for (int nt = 0; nt < 4; nt++) {
            const int n = n0 + warp_n*32 + nt*8 + c2;
            float* p0;
            float* p1;
            if (permute) {
                const int b = m >> 11, s = m & (S_ - 1);
                const int h = n >> 6, hd = n & (HD_ - 1);
                p0 = C + (((size_t)(b*H_ + h) * S_ + s) * HD_ + hd);
                p1 = C + (((size_t)(b*H_ + h) * S_ + (s + 8)) * HD_ + hd);
            } else {
                p0 = C + (size_t)m * D_ + n;
                p1 = C + (size_t)(m + 8) * D_ + n;
            }
            *reinterpret_cast<float2*>(p0) = make_float2(acc[mt][nt][0], acc[mt][nt][1]);
            *reinterpret_cast<float2*>(p1) = make_float2(acc[mt][nt][2], acc[mt][nt][3]);
        }
    }
}

// ===========================================================================
// Flash attention (fp32 SIMT, same as R1): one CTA per (b,h,64-row tile)
// ===========================================================================
#define TSTRIDE 68
#define ATTN_SMEM (4 * 64 * TSTRIDE * (int)sizeof(float))

__global__ __launch_bounds__(256) void attn_fwd(const float* __restrict__ XQ,
                                                const float* __restrict__ XK,
                                                const float* __restrict__ XV,
                                                float* __restrict__ O)
{
    extern __shared__ float sm[];
    float* Qst = sm;
    float* Kst = sm + 64*TSTRIDE;
    float* Vs  = sm + 2*64*TSTRIDE;
    float* Ps  = sm + 3*64*TSTRIDE;

    const int qb = blockIdx.x;
    const int h  = blockIdx.y;
    const int b  = blockIdx.z;
    const size_t base = (size_t)(b*H_ + h) * S_ * HD_;
    const float* Q = XQ + base;
    const float* K = XK + base;
    const float* V = XV + base;

    const int tid = threadIdx.x;
    const int tx = tid & 15, ty = tid >> 4;
    const int lr = tid >> 2, lq = tid & 3;
    const int q0 = qb * 64;

    {
        const float* src = Q + (size_t)(q0 + lr) * HD_ + lq*16;
        #pragma unroll
        for (int c = 0; c < 4; c++) {
            float4 v = reinterpret_cast<const float4*>(src)[c];
            int d = lq*16 + c*4;
            Qst[(d+0)*TSTRIDE + lr] = v.x * 0.125f;
            Qst[(d+1)*TSTRIDE + lr] = v.y * 0.125f;
            Qst[(d+2)*TSTRIDE + lr] = v.z * 0.125f;
            Qst[(d+3)*TSTRIDE + lr] = v.w * 0.125f;
        }
    }

    float oacc[4][4] = {};
    float mrow[4], lrow[4];
    #pragma unroll
    for (int i = 0; i < 4; i++) { mrow[i] = -1e30f; lrow[i] = 0.f; }

    for (int kb = 0; kb <= qb; kb++) {
        const int k0 = kb * 64;
        __syncthreads();
        {
            const float* srcK = K + (size_t)(k0 + lr) * HD_ + lq*16;
            const float* srcV = V + (size_t)(k0 + lr) * HD_ + lq*16;
            #pragma unroll
            for (int c = 0; c < 4; c++) {
                float4 kv = reinterpret_cast<const float4*>(srcK)[c];
                int d = lq*16 + c*4;
                Kst[(d+0)*TSTRIDE + lr] = kv.x;
                Kst[(d+1)*TSTRIDE + lr] = kv.y;
                Kst[(d+2)*TSTRIDE + lr] = kv.z;
                Kst[(d+3)*TSTRIDE + lr] = kv.w;
                float4 vv = reinterpret_cast<const float4*>(srcV)[c];
                *reinterpret_cast<float4*>(&Vs[lr*TSTRIDE + lq*16 + c*4]) = vv;
            }
        }
        __syncthreads();

        float sacc[4][4] = {};
        #pragma unroll 8
        for (int d = 0; d < 64; d++) {
            float4 a  = *reinterpret_cast<const float4*>(&Qst[d*TSTRIDE + ty*4]);
            float4 bv = *reinterpret_cast<const float4*>(&Kst[d*TSTRIDE + tx*4]);
            float av4[4] = {a.x, a.y, a.z, a.w};
            float bv4[4] = {bv.x, bv.y, bv.z, bv.w};
            #pragma unroll
            for (int i = 0; i < 4; i++)
                #pragma unroll
                for (int j = 0; j < 4; j++)
                    sacc[i][j] += av4[i] * bv4[j];
        }

        if (kb == qb) {
            #pragma unroll
            for (int i = 0; i < 4; i++)
                #pragma unroll
                for (int j = 0; j < 4; j++)
                    if (k0 + tx*4 + j > q0 + ty*4 + i) sacc[i][j] = -1e30f;
        }

        #pragma unroll
        for (int i = 0; i < 4; i++) {
            float rm = fmaxf(fmaxf(sacc[i][0], sacc[i][1]),
                             fmaxf(sacc[i][2], sacc[i][3]));
            #pragma unroll
            for (int off = 1; off < 16; off <<= 1)
                rm = fmaxf(rm, __shfl_xor_sync(0xffffffffu, rm, off));
            float mn   = fmaxf(mrow[i], rm);
            float corr = __expf(mrow[i] - mn);
            mrow[i] = mn;
            float rs = 0.f;
            #pragma unroll
            for (int j = 0; j < 4; j++) {
                float p = __expf(sacc[i][j] - mn);
                rs += p;
                Ps[(tx*4 + j)*TSTRIDE + ty*4 + i] = p;
            }
            #pragma unroll
            for (int off = 1; off < 16; off <<= 1)
                rs += __shfl_xor_sync(0xffffffffu, rs, off);
            lrow[i] = lrow[i]*corr + rs;
            #pragma unroll
            for (int j = 0; j < 4; j++) oacc[i][j] *= corr;
        }
        __syncthreads();

        #pragma unroll 8
        for (int j = 0; j < 64; j++) {
            float4 p  = *reinterpret_cast<const float4*>(&Ps[j*TSTRIDE + ty*4]);
            float4 vv = *reinterpret_cast<const float4*>(&Vs[j*TSTRIDE + tx*4]);
            float pv4[4] = {p.x, p.y, p.z, p.w};
            float vv4[4] = {vv.x, vv.y, vv.z, vv.w};
            #pragma unroll
            for (int i = 0; i < 4; i++)
                #pragma unroll
                for (int c = 0; c < 4; c++)
                    oacc[i][c] += pv4[i] * vv4[c];
        }
    }

    #pragma unroll
    for (int i = 0; i < 4; i++) {
        float inv = 1.f / lrow[i];
        size_t row = (size_t)(b * S_ + q0 + ty*4 + i) * D_ + h*HD_ + tx*4;
        #pragma unroll
        for (int j = 0; j < 4; j++)
            O[row + j] = oacc[i][j] * inv;
    }
}

// ===========================================================================
extern "C" void kernel_launch(void* const* d_in, const int* in_sizes, int n_in,
                              void* d_out, int out_size)
{
    const float* q  = (const float*)d_in[0];
    const float* k  = (const float*)d_in[1];
    const float* v  = (const float*)d_in[2];
    const float* wq = (const float*)d_in[3];
    const float* wk = (const float*)d_in[4];
    const float* wv = (const float*)d_in[5];
    const float* wo = (const float*)d_in[6];
    float* out = (float*)d_out;

    void *xq_p, *xk_p, *xv_p, *att_p;
    cudaGetSymbolAddress(&xq_p,  g_xq);
    cudaGetSymbolAddress(&xk_p,  g_xk);
    cudaGetSymbolAddress(&xv_p,  g_xv);
    cudaGetSymbolAddress(&att_p, g_att);

    cudaFuncSetAttribute(gemm_mma, cudaFuncAttributeMaxDynamicSharedMemorySize,
                         GSMEM);
    cudaFuncSetAttribute(attn_fwd, cudaFuncAttributeMaxDynamicSharedMemorySize,
                         ATTN_SMEM);

    dim3 ggrid(D_/128, M_/128);   // (8, 64)
    gemm_mma<<<ggrid, 256, GSMEM>>>(q, wq, (float*)xq_p, 1);
    gemm_mma<<<ggrid, 256, GSMEM>>>(k, wk, (float*)xk_p, 1);
    gemm_mma<<<ggrid, 256, GSMEM>>>(v, wv, (float*)xv_p, 1);

    dim3 agrid(S_/64, H_, B_);    // (32, 16, 4)
    attn_fwd<<<agrid, 256, ATTN_SMEM>>>((const float*)xq_p, (const float*)xk_p,
                                        (const float*)xv_p, (float*)att_p);

    gemm_mma<<<ggrid, 256, GSMEM>>>((const float*)att_p, wo, out, 0);
}

// round 4
// speedup vs baseline: 3.2455x; 1.8515x over previous
#include <cuda_runtime.h>
#include <cuda_bf16.h>
#include <cstdint>

#define B_  4
#define S_  2048
#define D_  1024
#define H_  16
#define HD_ 64
#define M_  (B_*S_)

// Scratch (device globals — no allocation allowed in kernel_launch)
__device__ __nv_bfloat16 g_qh[B_*H_*S_*HD_];
__device__ __nv_bfloat16 g_ql[B_*H_*S_*HD_];
__device__ __nv_bfloat16 g_kh[B_*H_*S_*HD_];
__device__ __nv_bfloat16 g_kl[B_*H_*S_*HD_];
__device__ __nv_bfloat16 g_vh[B_*H_*S_*HD_];
__device__ __nv_bfloat16 g_vl[B_*H_*S_*HD_];
__device__ float g_att[B_*S_*D_];      // [B,S,D]

// ===========================================================================
// Portable tensor-core helpers (compile under compute_103)
// ===========================================================================
__device__ __forceinline__ uint32_t smem_u32(const void* p) {
    uint32_t a;
    asm("{ .reg .u64 t; cvta.to.shared.u64 t, %1; cvt.u32.u64 %0, t; }"
        : "=r"(a) : "l"(p));
    return a;
}
// pack two fp32 -> bf16x2, lo_f in low half
__device__ __forceinline__ uint32_t packbf(float lo_f, float hi_f) {
    uint32_t r;
    asm("cvt.rn.bf16x2.f32 %0, %1, %2;" : "=r"(r) : "f"(hi_f), "f"(lo_f));
    return r;
}
__device__ __forceinline__ float lo16(uint32_t u) { return __uint_as_float(u << 16); }
__device__ __forceinline__ float hi16(uint32_t u) { return __uint_as_float(u & 0xffff0000u); }

__device__ __forceinline__ void ldm_x4(uint32_t* r, uint32_t a) {
    asm volatile("ldmatrix.sync.aligned.m8n8.x4.shared.b16 {%0,%1,%2,%3}, [%4];"
        : "=r"(r[0]), "=r"(r[1]), "=r"(r[2]), "=r"(r[3]) : "r"(a));
}
__device__ __forceinline__ void ldm_x4_t(uint32_t* r, uint32_t a) {
    asm volatile("ldmatrix.sync.aligned.m8n8.x4.trans.shared.b16 {%0,%1,%2,%3}, [%4];"
        : "=r"(r[0]), "=r"(r[1]), "=r"(r[2]), "=r"(r[3]) : "r"(a));
}
__device__ __forceinline__ void mma_bf(float* c, const uint32_t* a, const uint32_t* b) {
    asm volatile("mma.sync.aligned.m16n8k16.row.col.f32.bf16.bf16.f32 "
        "{%0,%1,%2,%3}, {%4,%5,%6,%7}, {%8,%9}, {%0,%1,%2,%3};"
        : "+f"(c[0]), "+f"(c[1]), "+f"(c[2]), "+f"(c[3])
        : "r"(a[0]), "r"(a[1]), "r"(a[2]), "r"(a[3]), "r"(b[0]), "r"(b[1]));
}
__device__ __forceinline__ void cpa16(uint32_t d, const void* s) {
    asm volatile("cp.async.ca.shared.global [%0], [%1], 16;" :: "r"(d), "l"(s));
}
__device__ __forceinline__ void cp_commit() {
    asm volatile("cp.async.commit_group;" ::: "memory");
}
__device__ __forceinline__ void cp_wait0() {
    asm volatile("cp.async.wait_group 0;" ::: "memory");
}

// Swizzled byte offset inside a 128x32-bf16 tile (64B rows, 16B chunks)
#define SWZB(row, ch) ((uint32_t)((row)*64 + ((((ch) ^ (((row)>>1)&3)))<<4)))

// fp32x8 -> bf16 hi chunk (16B) + lo chunk (16B)
__device__ __forceinline__ void cvt16(float4 x, float4 y, char* hip, char* lop) {
    uint32_t h0 = packbf(x.x, x.y), h1 = packbf(x.z, x.w);
    uint32_t h2 = packbf(y.x, y.y), h3 = packbf(y.z, y.w);
    float e0 = x.x - lo16(h0), e1 = x.y - hi16(h0);
    float e2 = x.z - lo16(h1), e3 = x.w - hi16(h1);
    float e4 = y.x - lo16(h2), e5 = y.y - hi16(h2);
    float e6 = y.z - lo16(h3), e7 = y.w - hi16(h3);
    *reinterpret_cast<uint4*>(hip) = make_uint4(h0, h1, h2, h3);
    *reinterpret_cast<uint4*>(lop) =
        make_uint4(packbf(e0,e1), packbf(e2,e3), packbf(e4,e5), packbf(e6,e7));
}

// ===========================================================================
// bf16x3 tensor-core GEMM: C[m,n] = sum_k A[m,k]*W[n,k]
// mode 0: fp32 out [M,D].  mode 1: bf16 hi/lo out [B,H,S,HD], scaled.
// ===========================================================================
#define GSTAGE 32768
#define GSMEM  (2*GSTAGE)

__global__ __launch_bounds__(256) void gemm_mma(const float* __restrict__ A,
                                                const float* __restrict__ W,
                                                float* __restrict__ C,
                                                __nv_bfloat16* __restrict__ Chi,
                                                __nv_bfloat16* __restrict__ Clo,
                                                int mode, float scale)
{
    extern __shared__ char smem[];
    const uint32_t sb = smem_u32(smem);
    const int tid = threadIdx.x, lane = tid & 31, wid = tid >> 5;
    const int warp_m = wid & 1, warp_n = wid >> 1;
    const int m0 = blockIdx.y * 128, n0 = blockIdx.x * 128;

    const int grow = tid >> 1, kp = tid & 1;
    const float* Ap = A + (size_t)(m0 + grow) * D_ + kp * 16;
    const float* Wp = W + (size_t)(n0 + grow) * D_ + kp * 16;
    const uint32_t o0 = SWZB(grow, kp*2);
    const uint32_t o1 = SWZB(grow, kp*2 + 1);

    const int arow = warp_m*64 + (lane & 15);
    const int akb  = lane >> 4;
    const int axr  = (arow >> 1) & 3;
    const int brow = warp_n*32 + ((lane >> 4) & 1) * 8 + (lane & 7);
    const int bkb  = (lane >> 3) & 1;
    const int bxr  = (brow >> 1) & 3;

    float acc[4][4][4];
    #pragma unroll
    for (int i = 0; i < 4; i++)
        #pragma unroll
        for (int j = 0; j < 4; j++)
            #pragma unroll
            for (int r = 0; r < 4; r++) acc[i][j][r] = 0.f;

    float4 fa0, fa1, fa2, fa3, fb0, fb1, fb2, fb3;
    fa0 = reinterpret_cast<const float4*>(Ap)[0];
    fa1 = reinterpret_cast<const float4*>(Ap)[1];
    fa2 = reinterpret_cast<const float4*>(Ap)[2];
    fa3 = reinterpret_cast<const float4*>(Ap)[3];
    fb0 = reinterpret_cast<const float4*>(Wp)[0];
    fb1 = reinterpret_cast<const float4*>(Wp)[1];
    fb2 = reinterpret_cast<const float4*>(Wp)[2];
    fb3 = reinterpret_cast<const float4*>(Wp)[3];

    for (int ch = 0; ch < 32; ch++) {
        char* sp = smem + (ch & 1) * GSTAGE;
        cvt16(fa0, fa1, sp + o0,         sp + 8192  + o0);
        cvt16(fa2, fa3, sp + o1,         sp + 8192  + o1);
        cvt16(fb0, fb1, sp + 16384 + o0, sp + 24576 + o0);
        cvt16(fb2, fb3, sp + 16384 + o1, sp + 24576 + o1);
        __syncthreads();
        if (ch < 31) {
            const float* pa = Ap + (ch + 1) * 32;
            const float* pb = Wp + (ch + 1) * 32;
            fa0 = reinterpret_cast<const float4*>(pa)[0];
            fa1 = reinterpret_cast<const float4*>(pa)[1];
            fa2 = reinterpret_cast<const float4*>(pa)[2];
            fa3 = reinterpret_cast<const float4*>(pa)[3];
            fb0 = reinterpret_cast<const float4*>(pb)[0];
            fb1 = reinterpret_cast<const float4*>(pb)[1];
            fb2 = reinterpret_cast<const float4*>(pb)[2];
            fb3 = reinterpret_cast<const float4*>(pb)[3];
        }
        const uint32_t ss = sb + (ch & 1) * GSTAGE;
        #pragma unroll
        for (int ks = 0; ks < 2; ks++) {
            uint32_t ah[4][4], al[4][4], bh[2][4], bl[2][4];
            #pragma unroll
            for (int mt = 0; mt < 4; mt++) {
                uint32_t ao = (uint32_t)((arow + mt*16)*64)
                            + ((uint32_t)((ks*2 + akb) ^ axr) << 4);
                ldm_x4(ah[mt], ss + ao);
                ldm_x4(al[mt], ss + 8192 + ao);
            }
            #pragma unroll
            for (int ntp = 0; ntp < 2; ntp++) {
                uint32_t bo = (uint32_t)((brow + ntp*16)*64)
                            + ((uint32_t)((ks*2 + bkb) ^ bxr) << 4);
                ldm_x4(bh[ntp], ss + 16384 + bo);
                ldm_x4(bl[ntp], ss + 24576 + bo);
            }
            #pragma unroll
            for (int mt = 0; mt < 4; mt++)
                #pragma unroll
                for (int nt = 0; nt < 4; nt++)
                    mma_bf(acc[mt][nt], ah[mt], &bh[nt >> 1][(nt & 1) * 2]);
            #pragma unroll
            for (int mt = 0; mt < 4; mt++)
                #pragma unroll
                for (int nt = 0; nt < 4; nt++)
                    mma_bf(acc[mt][nt], al[mt], &bh[nt >> 1][(nt & 1) * 2]);
            #pragma unroll
            for (int mt = 0; mt < 4; mt++)
                #pragma unroll
                for (int nt = 0; nt < 4; nt++)
                    mma_bf(acc[mt][nt], ah[mt], &bl[nt >> 1][(nt & 1) * 2]);
        }
    }

    const int r4 = lane >> 2, c2 = (lane & 3) * 2;
    #pragma unroll
    for (int mt = 0; mt < 4; mt++) {
        const int m = m0 + warp_m*64 + mt*16 + r4;
        #pragma unroll
        for (int nt = 0; nt < 4; nt++) {
            const int n = n0 + warp_n*32 + nt*8 + c2;
            if (mode == 1) {
                const int bb = m >> 11, s = m & (S_ - 1);
                const int hh = n >> 6, hd = n & (HD_ - 1);
                size_t i0 = ((size_t)(bb*H_ + hh) * S_ + s) * HD_ + hd;
                size_t i1 = i0 + 8*HD_;
                float v0 = acc[mt][nt][0]*scale, v1 = acc[mt][nt][1]*scale;
                float v2 = acc[mt][nt][2]*scale, v3 = acc[mt][nt][3]*scale;
                uint32_t ha = packbf(v0, v1);
                uint32_t la = packbf(v0 - lo16(ha), v1 - hi16(ha));
                uint32_t hb = packbf(v2, v3);
                uint32_t lb = packbf(v2 - lo16(hb), v3 - hi16(hb));
                *reinterpret_cast<uint32_t*>(Chi + i0) = ha;
                *reinterpret_cast<uint32_t*>(Clo + i0) = la;
                *reinterpret_cast<uint32_t*>(Chi + i1) = hb;
                *reinterpret_cast<uint32_t*>(Clo + i1) = lb;
            } else {
                float* p0 = C + (size_t)m * D_ + n;
                float* p1 = C + (size_t)(m + 8) * D_ + n;
                *reinterpret_cast<float2*>(p0) = make_float2(acc[mt][nt][0], acc[mt][nt][1]);
                *reinterpret_cast<float2*>(p1) = make_float2(acc[mt][nt][2], acc[mt][nt][3]);
            }
        }
    }
}

// ===========================================================================
// Tensor-core flash attention, bf16x3 split precision.
// CTA: 128 q-rows for one (b,h); 8 warps x 16 q-rows; kv blocks of 64,
// double-buffered via cp.async. Inputs pre-split bf16 hi/lo (Q pre-scaled).
// SMEM: Qh[0,16K) Ql[16K,32K) | stage s at 32K+s*32K: Kh,Kl,Vh,Vl (8KB each)
// ===========================================================================
#define AT_SMEM 98304

__global__ __launch_bounds__(256) void attn_mma(
    const __nv_bfloat16* __restrict__ Qh, const __nv_bfloat16* __restrict__ Ql,
    const __nv_bfloat16* __restrict__ Kh, const __nv_bfloat16* __restrict__ Kl,
    const __nv_bfloat16* __restrict__ Vh, const __nv_bfloat16* __restrict__ Vl,
    float* __restrict__ O)
{
    extern __shared__ char smem[];
    const uint32_t sb = smem_u32(smem);
    const int tid = threadIdx.x, lane = tid & 31, w = tid >> 5;
    const int qb = blockIdx.x, h = blockIdx.y, b = blockIdx.z;
    const int q0 = qb * 128;
    const size_t base = (size_t)(b*H_ + h) * S_ * HD_;

    // ---- prologue: Q tile + kv block 0 via cp.async ----
    #pragma unroll
    for (int i = 0; i < 4; i++) {
        int it = tid + i*256, row = it >> 3, ch = it & 7;
        uint32_t d = (uint32_t)(row*128 + ((ch ^ (row & 7)) << 4));
        size_t s = base + (size_t)(q0 + row)*HD_ + ch*8;
        cpa16(sb + d,         Qh + s);
        cpa16(sb + 16384 + d, Ql + s);
    }
    #pragma unroll
    for (int i = 0; i < 2; i++) {
        int it = tid + i*256, row = it >> 3, ch = it & 7;
        uint32_t d = (uint32_t)(row*128 + ((ch ^ (row & 7)) << 4));
        size_t s = base + (size_t)row*HD_ + ch*8;
        cpa16(sb + 32768 + d,         Kh + s);
        cpa16(sb + 32768 + 8192 + d,  Kl + s);
        cpa16(sb + 32768 + 16384 + d, Vh + s);
        cpa16(sb + 32768 + 24576 + d, Vl + s);
    }
    cp_commit();
    cp_wait0();
    __syncthreads();

    // ---- Q fragments (loop invariant) ----
    uint32_t aqh[4][4], aql[4][4];
    {
        const int row = w*16 + (lane & 15);
        #pragma unroll
        for (int ks = 0; ks < 4; ks++) {
            int kch = ks*2 + (lane >> 4);
            uint32_t ad = (uint32_t)(row*128 + ((kch ^ (row & 7)) << 4));
            ldm_x4(aqh[ks], sb + ad);
            ldm_x4(aql[ks], sb + 16384 + ad);
        }
    }

    float oacc[8][4];
    #pragma unroll
    for (int i = 0; i < 8; i++)
        #pragma unroll
        for (int j = 0; j < 4; j++) oacc[i][j] = 0.f;
    float m0 = -1e30f, m1 = -1e30f, l0 = 0.f, l1 = 0.f;
    const int qwr = q0 + w*16;
    const int nb = 2*qb + 2;

    for (int kb = 0; kb < nb; kb++) {
        const uint32_t st = 32768 + (uint32_t)(kb & 1) * 32768;
        if (kb + 1 < nb) {
            const uint32_t stn = 32768 + (uint32_t)((kb + 1) & 1) * 32768;
            const int k0n = (kb + 1) * 64;
            #pragma unroll
            for (int i = 0; i < 2; i++) {
                int it = tid + i*256, row = it >> 3, ch = it & 7;
                uint32_t d = (uint32_t)(row*128 + ((ch ^ (row & 7)) << 4));
                size_t s = base + (size_t)(k0n + row)*HD_ + ch*8;
                cpa16(sb + stn + d,         Kh + s);
                cpa16(sb + stn + 8192 + d,  Kl + s);
                cpa16(sb + stn + 16384 + d, Vh + s);
                cpa16(sb + stn + 24576 + d, Vl + s);
            }
            cp_commit();
        }
        const int k0 = kb * 64;

        if (k0 <= qwr + 15) {   // block not fully masked for this warp
            // ---- S = Q K^T ----
            float sc[8][4];
            #pragma unroll
            for (int i = 0; i < 8; i++)
                #pragma unroll
                for (int j = 0; j < 4; j++) sc[i][j] = 0.f;

            #pragma unroll
            for (int ks = 0; ks < 4; ks++) {
                #pragma unroll
                for (int ntp = 0; ntp < 4; ntp++) {
                    int nrow = ntp*16 + (lane & 7) + ((lane >> 4) & 1)*8;
                    int kch = ks*2 + ((lane >> 3) & 1);
                    uint32_t ad = (uint32_t)(nrow*128 + ((kch ^ (nrow & 7)) << 4));
                    uint32_t kh[4], kl[4];
                    ldm_x4(kh, sb + st + ad);
                    ldm_x4(kl, sb + st + 8192 + ad);
                    mma_bf(sc[2*ntp],   aqh[ks], kh);
                    mma_bf(sc[2*ntp+1], aqh[ks], kh + 2);
                    mma_bf(sc[2*ntp],   aql[ks], kh);
                    mma_bf(sc[2*ntp+1], aql[ks], kh + 2);
                    mma_bf(sc[2*ntp],   aqh[ks], kl);
                    mma_bf(sc[2*ntp+1], aqh[ks], kl + 2);
                }
            }

            // ---- causal mask ----
            const int r0g = qwr + (lane >> 2);
            if (k0 + 63 > qwr) {
                #pragma unroll
                for (int nt = 0; nt < 8; nt++) {
                    int c0 = k0 + nt*8 + (lane & 3)*2;
                    if (c0     > r0g)     sc[nt][0] = -1e30f;
                    if (c0 + 1 > r0g)     sc[nt][1] = -1e30f;
                    if (c0     > r0g + 8) sc[nt][2] = -1e30f;
                    if (c0 + 1 > r0g + 8) sc[nt][3] = -1e30f;
                }
            }

            // ---- online softmax ----
            float mx0 = -1e30f, mx1 = -1e30f;
            #pragma unroll
            for (int nt = 0; nt < 8; nt++) {
                mx0 = fmaxf(mx0, fmaxf(sc[nt][0], sc[nt][1]));
                mx1 = fmaxf(mx1, fmaxf(sc[nt][2], sc[nt][3]));
            }
            mx0 = fmaxf(mx0, __shfl_xor_sync(0xffffffffu, mx0, 1));
            mx0 = fmaxf(mx0, __shfl_xor_sync(0xffffffffu, mx0, 2));
            mx1 = fmaxf(mx1, __shfl_xor_sync(0xffffffffu, mx1, 1));
            mx1 = fmaxf(mx1, __shfl_xor_sync(0xffffffffu, mx1, 2));
            float mn0 = fmaxf(m0, mx0), mn1 = fmaxf(m1, mx1);
            float co0 = __expf(m0 - mn0), co1 = __expf(m1 - mn1);
            m0 = mn0; m1 = mn1;
            float rs0 = 0.f, rs1 = 0.f;
            #pragma unroll
            for (int nt = 0; nt < 8; nt++) {
                sc[nt][0] = __expf(sc[nt][0] - m0); rs0 += sc[nt][0];
                sc[nt][1] = __expf(sc[nt][1] - m0); rs0 += sc[nt][1];
                sc[nt][2] = __expf(sc[nt][2] - m1); rs1 += sc[nt][2];
                sc[nt][3] = __expf(sc[nt][3] - m1); rs1 += sc[nt][3];
            }
            rs0 += __shfl_xor_sync(0xffffffffu, rs0, 1);
            rs0 += __shfl_xor_sync(0xffffffffu, rs0, 2);
            rs1 += __shfl_xor_sync(0xffffffffu, rs1, 1);
            rs1 += __shfl_xor_sync(0xffffffffu, rs1, 2);
            l0 = l0*co0 + rs0;
            l1 = l1*co1 + rs1;
            #pragma unroll
            for (int nt = 0; nt < 8; nt++) {
                oacc[nt][0] *= co0; oacc[nt][1] *= co0;
                oacc[nt][2] *= co1; oacc[nt][3] *= co1;
            }

            // ---- O += P V ----
            #pragma unroll
            for (int ks = 0; ks < 4; ks++) {
                uint32_t aph[4], apl[4];
                aph[0] = packbf(sc[2*ks][0],   sc[2*ks][1]);
                aph[1] = packbf(sc[2*ks][2],   sc[2*ks][3]);
                aph[2] = packbf(sc[2*ks+1][0], sc[2*ks+1][1]);
                aph[3] = packbf(sc[2*ks+1][2], sc[2*ks+1][3]);
                apl[0] = packbf(sc[2*ks][0]   - lo16(aph[0]), sc[2*ks][1]   - hi16(aph[0]));
                apl[1] = packbf(sc[2*ks][2]   - lo16(aph[1]), sc[2*ks][3]   - hi16(aph[1]));
                apl[2] = packbf(sc[2*ks+1][0] - lo16(aph[2]), sc[2*ks+1][1] - hi16(aph[2]));
                apl[3] = packbf(sc[2*ks+1][2] - lo16(aph[3]), sc[2*ks+1][3] - hi16(aph[3]));
                #pragma unroll
                for (int np = 0; np < 4; np++) {
                    int kvr = ks*16 + ((lane >> 3) & 1)*8 + (lane & 7);
                    int nch = np*2 + (lane >> 4);
                    uint32_t ad = (uint32_t)(kvr*128 + ((nch ^ (kvr & 7)) << 4));
                    uint32_t vh[4], vl[4];
                    ldm_x4_t(vh, sb + st + 16384 + ad);
                    ldm_x4_t(vl, sb + st + 24576 + ad);
                    mma_bf(oacc[2*np],   aph, vh);
                    mma_bf(oacc[2*np+1], aph, vh + 2);
                    mma_bf(oacc[2*np],   apl, vh);
                    mma_bf(oacc[2*np+1], apl, vh + 2);
                    mma_bf(oacc[2*np],   aph, vl);
                    mma_bf(oacc[2*np+1], aph, vl + 2);
                }
            }
        }

        if (kb + 1 < nb) { cp_wait0(); __syncthreads(); }
    }

    // ---- epilogue ----
    const float i0 = 1.f / l0, i1 = 1.f / l1;
    const int r0g = qwr + (lane >> 2);
    #pragma unroll
    for (int nt = 0; nt < 8; nt++) {
        int col = h*HD_ + nt*8 + (lane & 3)*2;
        float* p0 = O + (size_t)(b*S_ + r0g) * D_ + col;
        float* p1 = O + (size_t)(b*S_ + r0g + 8) * D_ + col;
        *reinterpret_cast<float2*>(p0) = make_float2(oacc[nt][0]*i0, oacc[nt][1]*i0);
        *reinterpret_cast<float2*>(p1) = make_float2(oacc[nt][2]*i1, oacc[nt][3]*i1);
    }
}

// ===========================================================================
extern "C" void kernel_launch(void* const* d_in, const int* in_sizes, int n_in,
                              void* d_out, int out_size)
{
    const float* q  = (const float*)d_in[0];
    const float* k  = (const float*)d_in[1];
    const float* v  = (const float*)d_in[2];
    const float* wq = (const float*)d_in[3];
    const float* wk = (const float*)d_in[4];
    const float* wv = (const float*)d_in[5];
    const float* wo = (const float*)d_in[6];
    float* out = (float*)d_out;

    void *qh, *ql, *kh, *kl, *vh, *vl, *att;
    cudaGetSymbolAddress(&qh, g_qh);  cudaGetSymbolAddress(&ql, g_ql);
    cudaGetSymbolAddress(&kh, g_kh);  cudaGetSymbolAddress(&kl, g_kl);
    cudaGetSymbolAddress(&vh, g_vh);  cudaGetSymbolAddress(&vl, g_vl);
    cudaGetSymbolAddress(&att, g_att);

    cudaFuncSetAttribute(gemm_mma, cudaFuncAttributeMaxDynamicSharedMemorySize,
                         GSMEM);
    cudaFuncSetAttribute(attn_mma, cudaFuncAttributeMaxDynamicSharedMemorySize,
                         AT_SMEM);

    dim3 ggrid(D_/128, M_/128);   // (8, 64)
    gemm_mma<<<ggrid, 256, GSMEM>>>(q, wq, nullptr,
        (__nv_bfloat16*)qh, (__nv_bfloat16*)ql, 1, 0.125f);
    gemm_mma<<<ggrid, 256, GSMEM>>>(k, wk, nullptr,
        (__nv_bfloat16*)kh, (__nv_bfloat16*)kl, 1, 1.0f);
    gemm_mma<<<ggrid, 256, GSMEM>>>(v, wv, nullptr,
        (__nv_bfloat16*)vh, (__nv_bfloat16*)vl, 1, 1.0f);

    dim3 agrid(S_/128, H_, B_);   // (16, 16, 4)
    attn_mma<<<agrid, 256, AT_SMEM>>>(
        (const __nv_bfloat16*)qh, (const __nv_bfloat16*)ql,
        (const __nv_bfloat16*)kh, (const __nv_bfloat16*)kl,
        (const __nv_bfloat16*)vh, (const __nv_bfloat16*)vl,
        (float*)att);

    gemm_mma<<<ggrid, 256, GSMEM>>>((const float*)att, wo, out,
        nullptr, nullptr, 0, 1.0f);
}

// round 5
// speedup vs baseline: 3.6156x; 1.1141x over previous
#include <cuda_runtime.h>
#include <cuda_bf16.h>
#include <cstdint>

#define B_  4
#define S_  2048
#define D_  1024
#define H_  16
#define HD_ 64
#define M_  (B_*S_)

// Scratch (device globals)
__device__ __nv_bfloat16 g_iqh[M_*D_], g_iql[M_*D_];
__device__ __nv_bfloat16 g_ikh[M_*D_], g_ikl[M_*D_];
__device__ __nv_bfloat16 g_ivh[M_*D_], g_ivl[M_*D_];
__device__ __nv_bfloat16 g_wqh[D_*D_], g_wql[D_*D_];
__device__ __nv_bfloat16 g_wkh[D_*D_], g_wkl[D_*D_];
__device__ __nv_bfloat16 g_wvh[D_*D_], g_wvl[D_*D_];
__device__ __nv_bfloat16 g_woh[D_*D_], g_wol[D_*D_];
__device__ __nv_bfloat16 g_xqh[M_*D_], g_xql[M_*D_];
__device__ __nv_bfloat16 g_xkh[M_*D_], g_xkl[M_*D_];
__device__ __nv_bfloat16 g_xvh[M_*D_], g_xvl[M_*D_];
__device__ __nv_bfloat16 g_oh[M_*D_],  g_ol[M_*D_];

// ===========================================================================
// Helpers
// ===========================================================================
__device__ __forceinline__ uint32_t smem_u32(const void* p) {
    uint32_t a;
    asm("{ .reg .u64 t; cvta.to.shared.u64 t, %1; cvt.u32.u64 %0, t; }"
        : "=r"(a) : "l"(p));
    return a;
}
__device__ __forceinline__ uint32_t packbf(float lo_f, float hi_f) {
    uint32_t r;
    asm("cvt.rn.bf16x2.f32 %0, %1, %2;" : "=r"(r) : "f"(hi_f), "f"(lo_f));
    return r;
}
__device__ __forceinline__ float lo16(uint32_t u) { return __uint_as_float(u << 16); }
__device__ __forceinline__ float hi16(uint32_t u) { return __uint_as_float(u & 0xffff0000u); }
__device__ __forceinline__ float ex2(float x) {
    float r; asm("ex2.approx.f32 %0, %1;" : "=f"(r) : "f"(x)); return r;
}
__device__ __forceinline__ void ldm_x4(uint32_t* r, uint32_t a) {
    asm volatile("ldmatrix.sync.aligned.m8n8.x4.shared.b16 {%0,%1,%2,%3}, [%4];"
        : "=r"(r[0]), "=r"(r[1]), "=r"(r[2]), "=r"(r[3]) : "r"(a));
}
__device__ __forceinline__ void ldm_x4_t(uint32_t* r, uint32_t a) {
    asm volatile("ldmatrix.sync.aligned.m8n8.x4.trans.shared.b16 {%0,%1,%2,%3}, [%4];"
        : "=r"(r[0]), "=r"(r[1]), "=r"(r[2]), "=r"(r[3]) : "r"(a));
}
__device__ __forceinline__ void mma_bf(float* c, const uint32_t* a, const uint32_t* b) {
    asm volatile("mma.sync.aligned.m16n8k16.row.col.f32.bf16.bf16.f32 "
        "{%0,%1,%2,%3}, {%4,%5,%6,%7}, {%8,%9}, {%0,%1,%2,%3};"
        : "+f"(c[0]), "+f"(c[1]), "+f"(c[2]), "+f"(c[3])
        : "r"(a[0]), "r"(a[1]), "r"(a[2]), "r"(a[3]), "r"(b[0]), "r"(b[1]));
}
__device__ __forceinline__ void cpa16(uint32_t d, const void* s) {
    asm volatile("cp.async.ca.shared.global [%0], [%1], 16;" :: "r"(d), "l"(s));
}
__device__ __forceinline__ void cp_commit() {
    asm volatile("cp.async.commit_group;" ::: "memory");
}
__device__ __forceinline__ void cp_wait0() {
    asm volatile("cp.async.wait_group 0;" ::: "memory");
}
__device__ __forceinline__ void cp_wait1() {
    asm volatile("cp.async.wait_group 1;" ::: "memory");
}

// Swizzled byte offset inside a 128x32-bf16 tile (64B rows, 16B chunks)
#define SWZB(row, ch) ((uint32_t)((row)*64 + ((((ch) ^ (((row)>>1)&3)))<<4)))

// ===========================================================================
// fp32 -> bf16 hi/lo split kernels
// ===========================================================================
__device__ __forceinline__ void split4(float4 v, uint2* hp, uint2* lp) {
    uint32_t h0 = packbf(v.x, v.y), h1 = packbf(v.z, v.w);
    *hp = make_uint2(h0, h1);
    *lp = make_uint2(packbf(v.x - lo16(h0), v.y - hi16(h0)),
                     packbf(v.z - lo16(h1), v.w - hi16(h1)));
}
__global__ __launch_bounds__(256) void split3(
    const float4* __restrict__ a, const float4* __restrict__ b,
    const float4* __restrict__ c,
    uint2* ah, uint2* al, uint2* bh, uint2* bl, uint2* ch, uint2* cl)
{
    int i = blockIdx.x * 256 + threadIdx.x;
    const float4* src; uint2 *ph, *pl;
    if (blockIdx.y == 0)      { src = a; ph = ah; pl = al; }
    else if (blockIdx.y == 1) { src = b; ph = bh; pl = bl; }
    else                      { src = c; ph = ch; pl = cl; }
    split4(src[i], ph + i, pl + i);
}
__global__ __launch_bounds__(256) void split1(
    const float4* __restrict__ a, uint2* ah, uint2* al)
{
    int i = blockIdx.x * 256 + threadIdx.x;
    split4(a[i], ah + i, al + i);
}

// ===========================================================================
// bf16x3 GEMM v2: C[m,n] = sum_k A[m,k]*W[n,k]; inputs pre-split bf16 hi/lo.
// CTA 128x128, BK=32, 8 warps, 3-stage cp.async pipeline (32KB/stage).
// MODE 1: bf16 hi/lo out, [B,H,S,HD] permuted, scaled. MODE 0: fp32 out [M,D].
// ===========================================================================
#define NS 3
#define GST 32768
#define GSM2 (NS*GST)

struct GemmArgs {
    const __nv_bfloat16 *Ah[3], *Al[3], *Wh[3], *Wl[3];
    __nv_bfloat16 *Ch[3], *Cl[3];
    float scale[3];
};

template <int MODE>
__global__ __launch_bounds__(256) void gemm2(GemmArgs ga, float* __restrict__ Cf)
{
    extern __shared__ char smem[];
    const uint32_t sb = smem_u32(smem);
    const int tid = threadIdx.x, lane = tid & 31, wid = tid >> 5;
    const int warp_m = wid & 1, warp_n = wid >> 1;
    const int m0 = blockIdx.y * 128, n0 = blockIdx.x * 128;
    const int z = blockIdx.z;

    const __nv_bfloat16* Ah_ = ga.Ah[z];
    const __nv_bfloat16* Al_ = ga.Al[z];
    const __nv_bfloat16* Wh_ = ga.Wh[z];
    const __nv_bfloat16* Wl_ = ga.Wl[z];

    // cp.async mapping: thread handles 2 chunks (16B each) per 8KB tile
    const int lrow = tid >> 1, lch = (tid & 1) * 2;
    const __nv_bfloat16* pAh = Ah_ + (size_t)(m0 + lrow) * D_ + lch * 8;
    const __nv_bfloat16* pAl = Al_ + (size_t)(m0 + lrow) * D_ + lch * 8;
    const __nv_bfloat16* pBh = Wh_ + (size_t)(n0 + lrow) * D_ + lch * 8;
    const __nv_bfloat16* pBl = Wl_ + (size_t)(n0 + lrow) * D_ + lch * 8;
    const uint32_t d0 = SWZB(lrow, lch), d1 = SWZB(lrow, lch + 1);

    #define G2_ISSUE(kc, slot) do {                                        \
        const uint32_t s_ = sb + (uint32_t)(slot) * GST;                   \
        const int ko_ = (kc) * 32;                                         \
        cpa16(s_ + d0,          pAh + ko_);                                \
        cpa16(s_ + d1,          pAh + ko_ + 8);                            \
        cpa16(s_ + 8192  + d0,  pAl + ko_);                                \
        cpa16(s_ + 8192  + d1,  pAl + ko_ + 8);                            \
        cpa16(s_ + 16384 + d0,  pBh + ko_);                                \
        cpa16(s_ + 16384 + d1,  pBh + ko_ + 8);                            \
        cpa16(s_ + 24576 + d0,  pBl + ko_);                                \
        cpa16(s_ + 24576 + d1,  pBl + ko_ + 8);                            \
        cp_commit();                                                       \
    } while (0)

    // ldmatrix address components (validated R3/R4)
    const int arow = warp_m*64 + (lane & 15);
    const int akb  = lane >> 4;
    const int axr  = (arow >> 1) & 3;
    const int brow = warp_n*32 + ((lane >> 4) & 1) * 8 + (lane & 7);
    const int bkb  = (lane >> 3) & 1;
    const int bxr  = (brow >> 1) & 3;

    float acc[4][4][4];
    #pragma unroll
    for (int i = 0; i < 4; i++)
        #pragma unroll
        for (int j = 0; j < 4; j++)
            #pragma unroll
            for (int r = 0; r < 4; r++) acc[i][j][r] = 0.f;

    G2_ISSUE(0, 0);
    G2_ISSUE(1, 1);

    for (int ch = 0; ch < 32; ch++) {
        cp_wait1();
        __syncthreads();
        const uint32_t ss = sb + (uint32_t)(ch % NS) * GST;
        #pragma unroll
        for (int ks = 0; ks < 2; ks++) {
            uint32_t ah[4][4], al[4][4], bh[2][4], bl[2][4];
            #pragma unroll
            for (int mt = 0; mt < 4; mt++) {
                uint32_t ao = (uint32_t)((arow + mt*16)*64)
                            + ((uint32_t)((ks*2 + akb) ^ axr) << 4);
                ldm_x4(ah[mt], ss + ao);
                ldm_x4(al[mt], ss + 8192 + ao);
            }
            #pragma unroll
            for (int ntp = 0; ntp < 2; ntp++) {
                uint32_t bo = (uint32_t)((brow + ntp*16)*64)
                            + ((uint32_t)((ks*2 + bkb) ^ bxr) << 4);
                ldm_x4(bh[ntp], ss + 16384 + bo);
                ldm_x4(bl[ntp], ss + 24576 + bo);
            }
            #pragma unroll
            for (int mt = 0; mt < 4; mt++)
                #pragma unroll
                for (int nt = 0; nt < 4; nt++)
                    mma_bf(acc[mt][nt], ah[mt], &bh[nt >> 1][(nt & 1) * 2]);
            #pragma unroll
            for (int mt = 0; mt < 4; mt++)
                #pragma unroll
                for (int nt = 0; nt < 4; nt++)
                    mma_bf(acc[mt][nt], al[mt], &bh[nt >> 1][(nt & 1) * 2]);
            #pragma unroll
            for (int mt = 0; mt < 4; mt++)
                #pragma unroll
                for (int nt = 0; nt < 4; nt++)
                    mma_bf(acc[mt][nt], ah[mt], &bl[nt >> 1][(nt & 1) * 2]);
        }
        if (ch + 2 < 32) G2_ISSUE(ch + 2, (ch + 2) % NS);
    }

    const int r4 = lane >> 2, c2 = (lane & 3) * 2;
    const float scale = ga.scale[z];
    #pragma unroll
    for (int mt = 0; mt < 4; mt++) {
        const int m = m0 + warp_m*64 + mt*16 + r4;
        #pragma unroll
        for (int nt = 0; nt < 4; nt++) {
            const int n = n0 + warp_n*32 + nt*8 + c2;
            if (MODE == 1) {
                __nv_bfloat16* Chi = ga.Ch[z];
                __nv_bfloat16* Clo = ga.Cl[z];
                const int bb = m >> 11, s = m & (S_ - 1);
                const int hh = n >> 6, hd = n & (HD_ - 1);
                size_t i0 = ((size_t)(bb*H_ + hh) * S_ + s) * HD_ + hd;
                size_t i1 = i0 + 8*HD_;
                float v0 = acc[mt][nt][0]*scale, v1 = acc[mt][nt][1]*scale;
                float v2 = acc[mt][nt][2]*scale, v3 = acc[mt][nt][3]*scale;
                uint32_t ha = packbf(v0, v1);
                uint32_t la = packbf(v0 - lo16(ha), v1 - hi16(ha));
                uint32_t hb = packbf(v2, v3);
                uint32_t lb = packbf(v2 - lo16(hb), v3 - hi16(hb));
                *reinterpret_cast<uint32_t*>(Chi + i0) = ha;
                *reinterpret_cast<uint32_t*>(Clo + i0) = la;
                *reinterpret_cast<uint32_t*>(Chi + i1) = hb;
                *reinterpret_cast<uint32_t*>(Clo + i1) = lb;
            } else {
                float* p0 = Cf + (size_t)m * D_ + n;
                float* p1 = Cf + (size_t)(m + 8) * D_ + n;
                *reinterpret_cast<float2*>(p0) = make_float2(acc[mt][nt][0], acc[mt][nt][1]);
                *reinterpret_cast<float2*>(p1) = make_float2(acc[mt][nt][2], acc[mt][nt][3]);
            }
        }
    }
}

// ===========================================================================
// Tensor-core flash attention, bf16x3; log2-domain softmax (Q pre-scaled by
// 0.125*log2e). Outputs bf16 hi/lo [B,S,D]. SMEM 64KB: Q loaded into stage
// area first, fragments extracted, then region reused for 2 KV stages.
// ===========================================================================
#define AT_SMEM 65536

__global__ __launch_bounds__(256, 2) void attn_mma(
    const __nv_bfloat16* __restrict__ Qh, const __nv_bfloat16* __restrict__ Ql,
    const __nv_bfloat16* __restrict__ Kh, const __nv_bfloat16* __restrict__ Kl,
    const __nv_bfloat16* __restrict__ Vh, const __nv_bfloat16* __restrict__ Vl,
    __nv_bfloat16* __restrict__ Ohi, __nv_bfloat16* __restrict__ Olo)
{
    extern __shared__ char smem[];
    const uint32_t sb = smem_u32(smem);
    const int tid = threadIdx.x, lane = tid & 31, w = tid >> 5;
    const int qb = blockIdx.x, h = blockIdx.y, b = blockIdx.z;
    const int q0 = qb * 128;
    const size_t base = (size_t)(b*H_ + h) * S_ * HD_;

    // ---- Q into [0,32K) ----
    #pragma unroll
    for (int i = 0; i < 4; i++) {
        int it = tid + i*256, row = it >> 3, ch = it & 7;
        uint32_t d = (uint32_t)(row*128 + ((ch ^ (row & 7)) << 4));
        size_t s = base + (size_t)(q0 + row)*HD_ + ch*8;
        cpa16(sb + d,         Qh + s);
        cpa16(sb + 16384 + d, Ql + s);
    }
    cp_commit();
    cp_wait0();
    __syncthreads();

    // ---- Q fragments ----
    uint32_t aqh[4][4], aql[4][4];
    {
        const int row = w*16 + (lane & 15);
        #pragma unroll
        for (int ks = 0; ks < 4; ks++) {
            int kch = ks*2 + (lane >> 4);
            uint32_t ad = (uint32_t)(row*128 + ((kch ^ (row & 7)) << 4));
            ldm_x4(aqh[ks], sb + ad);
            ldm_x4(aql[ks], sb + 16384 + ad);
        }
    }
    __syncthreads();   // all warps done reading Q before stage reuse

    // ---- KV block 0 into stage 0 ----
    #pragma unroll
    for (int i = 0; i < 2; i++) {
        int it = tid + i*256, row = it >> 3, ch = it & 7;
        uint32_t d = (uint32_t)(row*128 + ((ch ^ (row & 7)) << 4));
        size_t s = base + (size_t)row*HD_ + ch*8;
        cpa16(sb + d,         Kh + s);
        cpa16(sb + 8192 + d,  Kl + s);
        cpa16(sb + 16384 + d, Vh + s);
        cpa16(sb + 24576 + d, Vl + s);
    }
    cp_commit();
    cp_wait0();
    __syncthreads();

    float oacc[8][4];
    #pragma unroll
    for (int i = 0; i < 8; i++)
        #pragma unroll
        for (int j = 0; j < 4; j++) oacc[i][j] = 0.f;
    float m0 = -1e30f, m1 = -1e30f, l0 = 0.f, l1 = 0.f;
    const int qwr = q0 + w*16;
    const int nb = 2*qb + 2;

    for (int kb = 0; kb < nb; kb++) {
        const uint32_t st = (uint32_t)(kb & 1) * 32768;
        if (kb + 1 < nb) {
            const uint32_t stn = (uint32_t)((kb + 1) & 1) * 32768;
            const int k0n = (kb + 1) * 64;
            #pragma unroll
            for (int i = 0; i < 2; i++) {
                int it = tid + i*256, row = it >> 3, ch = it & 7;
                uint32_t d = (uint32_t)(row*128 + ((ch ^ (row & 7)) << 4));
                size_t s = base + (size_t)(k0n + row)*HD_ + ch*8;
                cpa16(sb + stn + d,         Kh + s);
                cpa16(sb + stn + 8192 + d,  Kl + s);
                cpa16(sb + stn + 16384 + d, Vh + s);
                cpa16(sb + stn + 24576 + d, Vl + s);
            }
            cp_commit();
        }
        const int k0 = kb * 64;

        if (k0 <= qwr + 15) {
            // ---- S = Q K^T (log2 units) ----
            float sc[8][4];
            #pragma unroll
            for (int i = 0; i < 8; i++)
                #pragma unroll
                for (int j = 0; j < 4; j++) sc[i][j] = 0.f;

            #pragma unroll
            for (int ks = 0; ks < 4; ks++) {
                #pragma unroll
                for (int ntp = 0; ntp < 4; ntp++) {
                    int nrow = ntp*16 + (lane & 7) + ((lane >> 4) & 1)*8;
                    int kch = ks*2 + ((lane >> 3) & 1);
                    uint32_t ad = (uint32_t)(nrow*128 + ((kch ^ (nrow & 7)) << 4));
                    uint32_t kh[4], kl[4];
                    ldm_x4(kh, sb + st + ad);
                    ldm_x4(kl, sb + st + 8192 + ad);
                    mma_bf(sc[2*ntp],   aqh[ks], kh);
                    mma_bf(sc[2*ntp+1], aqh[ks], kh + 2);
                    mma_bf(sc[2*ntp],   aql[ks], kh);
                    mma_bf(sc[2*ntp+1], aql[ks], kh + 2);
                    mma_bf(sc[2*ntp],   aqh[ks], kl);
                    mma_bf(sc[2*ntp+1], aqh[ks], kl + 2);
                }
            }

            // ---- causal mask ----
            const int r0g = qwr + (lane >> 2);
            if (k0 + 63 > qwr) {
                #pragma unroll
                for (int nt = 0; nt < 8; nt++) {
                    int c0 = k0 + nt*8 + (lane & 3)*2;
                    if (c0     > r0g)     sc[nt][0] = -1e30f;
                    if (c0 + 1 > r0g)     sc[nt][1] = -1e30f;
                    if (c0     > r0g + 8) sc[nt][2] = -1e30f;
                    if (c0 + 1 > r0g + 8) sc[nt][3] = -1e30f;
                }
            }

            // ---- online softmax (base-2) ----
            float mx0 = -1e30f, mx1 = -1e30f;
            #pragma unroll
            for (int nt = 0; nt < 8; nt++) {
                mx0 = fmaxf(mx0, fmaxf(sc[nt][0], sc[nt][1]));
                mx1 = fmaxf(mx1, fmaxf(sc[nt][2], sc[nt][3]));
            }
            mx0 = fmaxf(mx0, __shfl_xor_sync(0xffffffffu, mx0, 1));
            mx0 = fmaxf(mx0, __shfl_xor_sync(0xffffffffu, mx0, 2));
            mx1 = fmaxf(mx1, __shfl_xor_sync(0xffffffffu, mx1, 1));
            mx1 = fmaxf(mx1, __shfl_xor_sync(0xffffffffu, mx1, 2));
            float mn0 = fmaxf(m0, mx0), mn1 = fmaxf(m1, mx1);
            float co0 = ex2(m0 - mn0), co1 = ex2(m1 - mn1);
            m0 = mn0; m1 = mn1;
            float rs0 = 0.f, rs1 = 0.f;
            #pragma unroll
            for (int nt = 0; nt < 8; nt++) {
                sc[nt][0] = ex2(sc[nt][0] - m0); rs0 += sc[nt][0];
                sc[nt][1] = ex2(sc[nt][1] - m0); rs0 += sc[nt][1];
                sc[nt][2] = ex2(sc[nt][2] - m1); rs1 += sc[nt][2];
                sc[nt][3] = ex2(sc[nt][3] - m1); rs1 += sc[nt][3];
            }
            rs0 += __shfl_xor_sync(0xffffffffu, rs0, 1);
            rs0 += __shfl_xor_sync(0xffffffffu, rs0, 2);
            rs1 += __shfl_xor_sync(0xffffffffu, rs1, 1);
            rs1 += __shfl_xor_sync(0xffffffffu, rs1, 2);
            l0 = l0*co0 + rs0;
            l1 = l1*co1 + rs1;
            #pragma unroll
            for (int nt = 0; nt < 8; nt++) {
                oacc[nt][0] *= co0; oacc[nt][1] *= co0;
                oacc[nt][2] *= co1; oacc[nt][3] *= co1;
            }

            // ---- O += P V ----
            #pragma unroll
            for (int ks = 0; ks < 4; ks++) {
                uint32_t aph[4], apl[4];
                aph[0] = packbf(sc[2*ks][0],   sc[2*ks][1]);
                aph[1] = packbf(sc[2*ks][2],   sc[2*ks][3]);
                aph[2] = packbf(sc[2*ks+1][0], sc[2*ks+1][1]);
                aph[3] = packbf(sc[2*ks+1][2], sc[2*ks+1][3]);
                apl[0] = packbf(sc[2*ks][0]   - lo16(aph[0]), sc[2*ks][1]   - hi16(aph[0]));
                apl[1] = packbf(sc[2*ks][2]   - lo16(aph[1]), sc[2*ks][3]   - hi16(aph[1]));
                apl[2] = packbf(sc[2*ks+1][0] - lo16(aph[2]), sc[2*ks+1][1] - hi16(aph[2]));
                apl[3] = packbf(sc[2*ks+1][2] - lo16(aph[3]), sc[2*ks+1][3] - hi16(aph[3]));
                #pragma unroll
                for (int np = 0; np < 4; np++) {
                    int kvr = ks*16 + ((lane >> 3) & 1)*8 + (lane & 7);
                    int nch = np*2 + (lane >> 4);
                    uint32_t ad = (uint32_t)(kvr*128 + ((nch ^ (kvr & 7)) << 4));
                    uint32_t vh[4], vl[4];
                    ldm_x4_t(vh, sb + st + 16384 + ad);
                    ldm_x4_t(vl, sb + st + 24576 + ad);
                    mma_bf(oacc[2*np],   aph, vh);
                    mma_bf(oacc[2*np+1], aph, vh + 2);
                    mma_bf(oacc[2*np],   apl, vh);
                    mma_bf(oacc[2*np+1], apl, vh + 2);
                    mma_bf(oacc[2*np],   aph, vl);
                    mma_bf(oacc[2*np+1], aph, vl + 2);
                }
            }
        }

        if (kb + 1 < nb) { cp_wait0(); __syncthreads(); }
    }

    // ---- epilogue: write bf16 hi/lo [B,S,D] ----
    const float i0v = 1.f / l0, i1v = 1.f / l1;
    const int r0g = qwr + (lane >> 2);
    #pragma unroll
    for (int nt = 0; nt < 8; nt++) {
        int col = h*HD_ + nt*8 + (lane & 3)*2;
        size_t e0 = (size_t)(b*S_ + r0g) * D_ + col;
        size_t e1 = e0 + (size_t)8 * D_;
        float x0 = oacc[nt][0]*i0v, x1 = oacc[nt][1]*i0v;
        float x2 = oacc[nt][2]*i1v, x3 = oacc[nt][3]*i1v;
        uint32_t ha = packbf(x0, x1);
        uint32_t la = packbf(x0 - lo16(ha), x1 - hi16(ha));
        uint32_t hb = packbf(x2, x3);
        uint32_t lb = packbf(x2 - lo16(hb), x3 - hi16(hb));
        *reinterpret_cast<uint32_t*>(Ohi + e0) = ha;
        *reinterpret_cast<uint32_t*>(Olo + e0) = la;
        *reinterpret_cast<uint32_t*>(Ohi + e1) = hb;
        *reinterpret_cast<uint32_t*>(Olo + e1) = lb;
    }
}

// ===========================================================================
extern "C" void kernel_launch(void* const* d_in, const int* in_sizes, int n_in,
                              void* d_out, int out_size)
{
    const float* q  = (const float*)d_in[0];
    const float* k  = (const float*)d_in[1];
    const float* v  = (const float*)d_in[2];
    const float* wq = (const float*)d_in[3];
    const float* wk = (const float*)d_in[4];
    const float* wv = (const float*)d_in[5];
    const float* wo = (const float*)d_in[6];
    float* out = (float*)d_out;

    #define SYM(p, s) void* p; cudaGetSymbolAddress(&p, s)
    SYM(iqh, g_iqh); SYM(iql, g_iql);
    SYM(ikh, g_ikh); SYM(ikl, g_ikl);
    SYM(ivh, g_ivh); SYM(ivl, g_ivl);
    SYM(wqh, g_wqh); SYM(wql, g_wql);
    SYM(wkh, g_wkh); SYM(wkl, g_wkl);
    SYM(wvh, g_wvh); SYM(wvl, g_wvl);
    SYM(woh, g_woh); SYM(wol, g_wol);
    SYM(xqh, g_xqh); SYM(xql, g_xql);
    SYM(xkh, g_xkh); SYM(xkl, g_xkl);
    SYM(xvh, g_xvh); SYM(xvl, g_xvl);
    SYM(oh,  g_oh);  SYM(ol,  g_ol);
    #undef SYM

    cudaFuncSetAttribute(gemm2<1>, cudaFuncAttributeMaxDynamicSharedMemorySize, GSM2);
    cudaFuncSetAttribute(gemm2<0>, cudaFuncAttributeMaxDynamicSharedMemorySize, GSM2);
    cudaFuncSetAttribute(attn_mma, cudaFuncAttributeMaxDynamicSharedMemorySize, AT_SMEM);

    // --- split inputs + weights to bf16 hi/lo ---
    dim3 sg3(M_*D_/1024, 3);
    split3<<<sg3, 256>>>((const float4*)q, (const float4*)k, (const float4*)v,
        (uint2*)iqh, (uint2*)iql, (uint2*)ikh, (uint2*)ikl, (uint2*)ivh, (uint2*)ivl);
    split1<<<D_*D_/1024, 256>>>((const float4*)wq, (uint2*)wqh, (uint2*)wql);
    split1<<<D_*D_/1024, 256>>>((const float4*)wk, (uint2*)wkh, (uint2*)wkl);
    split1<<<D_*D_/1024, 256>>>((const float4*)wv, (uint2*)wvh, (uint2*)wvl);
    split1<<<D_*D_/1024, 256>>>((const float4*)wo, (uint2*)woh, (uint2*)wol);

    // --- merged QKV projection GEMM (z = q,k,v) ---
    GemmArgs gq = {};
    gq.Ah[0] = (const __nv_bfloat16*)iqh; gq.Al[0] = (const __nv_bfloat16*)iql;
    gq.Ah[1] = (const __nv_bfloat16*)ikh; gq.Al[1] = (const __nv_bfloat16*)ikl;
    gq.Ah[2] = (const __nv_bfloat16*)ivh; gq.Al[2] = (const __nv_bfloat16*)ivl;
    gq.Wh[0] = (const __nv_bfloat16*)wqh; gq.Wl[0] = (const __nv_bfloat16*)wql;
    gq.Wh[1] = (const __nv_bfloat16*)wkh; gq.Wl[1] = (const __nv_bfloat16*)wkl;
    gq.Wh[2] = (const __nv_bfloat16*)wvh; gq.Wl[2] = (const __nv_bfloat16*)wvl;
    gq.Ch[0] = (__nv_bfloat16*)xqh; gq.Cl[0] = (__nv_bfloat16*)xql;
    gq.Ch[1] = (__nv_bfloat16*)xkh; gq.Cl[1] = (__nv_bfloat16*)xkl;
    gq.Ch[2] = (__nv_bfloat16*)xvh; gq.Cl[2] = (__nv_bfloat16*)xvl;
    gq.scale[0] = 0.125f * 1.44269504089f;   // fold 1/sqrt(64) * log2(e) into Q
    gq.scale[1] = 1.0f;
    gq.scale[2] = 1.0f;
    dim3 ggrid(D_/128, M_/128, 3);   // (8, 64, 3)
    gemm2<1><<<ggrid, 256, GSM2>>>(gq, nullptr);

    // --- attention ---
    dim3 agrid(S_/128, H_, B_);      // (16, 16, 4)
    attn_mma<<<agrid, 256, AT_SMEM>>>(
        (const __nv_bfloat16*)xqh, (const __nv_bfloat16*)xql,
        (const __nv_bfloat16*)xkh, (const __nv_bfloat16*)xkl,
        (const __nv_bfloat16*)xvh, (const __nv_bfloat16*)xvl,
        (__nv_bfloat16*)oh, (__nv_bfloat16*)ol);

    // --- output projection ---
    GemmArgs go = {};
    go.Ah[0] = (const __nv_bfloat16*)oh;  go.Al[0] = (const __nv_bfloat16*)ol;
    go.Wh[0] = (const __nv_bfloat16*)woh; go.Wl[0] = (const __nv_bfloat16*)wol;
    go.scale[0] = 1.0f;
    dim3 fgrid(D_/128, M_/128, 1);
    gemm2<0><<<fgrid, 256, GSM2>>>(go, out);
}